// round 4
// baseline (speedup 1.0000x reference)
#include <cuda_runtime.h>

// CapsuleLayer dynamic routing, factored (u_hat never materialized), f32x2 packed math.
// X[B=128, I=1152, J=128], W[J=128, K=32, D=32], out V[B=128, K=32, D=32]
//
// it0:  y = colsum(x)/32 ; s,v,T
// trans 0,1 (one fused streaming pass over x, per 64-i chunk):
//   GEMM2: bl[k,i] (+)= sum_j x[i,j] T[k,j]   -> blc (smem) + blg (gmem)
//   softmax_k(blc) -> c2 (duplicated pairs)
//   GEMM1: y[k,j] += sum_i c[i,k] x[i,j]      (register accumulators)
// then s = y*W, v = squash(s); trans0 -> T, trans1 -> out.

#define BB 128
#define II 1152
#define JJ 128
#define KK 32
#define DD 32
#define KD 1024
#define CI 64
#define NCHUNK 18
#define XPF 132          // x smem pitch (floats)
#define XBUF (CI*XPF)    // 8448 floats per buffer
#define C2P 68
#define NT 512

typedef unsigned long long u64;

#define FMA2(d,a,b,c) asm("fma.rn.f32x2 %0, %1, %2, %3;" : "=l"(d) : "l"(a), "l"(b), "l"(c))
#define ADD2(d,a,b)   asm("add.rn.f32x2 %0, %1, %2;" : "=l"(d) : "l"(a), "l"(b))
#define MUL2(d,a,b)   asm("mul.rn.f32x2 %0, %1, %2;" : "=l"(d) : "l"(a), "l"(b))
#define CP_COMMIT()   asm volatile("cp.async.commit_group;\n" ::: "memory")
#define CP_WAIT0()    asm volatile("cp.async.wait_group 0;\n" ::: "memory")

// routing logits scratch [b][k][i]
__device__ float g_bl[(size_t)BB * KK * II];

// smem float offsets
#define SM_XS  0         // 2 x 8448 = 16896      (also 16x 32x33 W-transpose scratch)
#define SM_C2  16896     // 64*68 = 4352          softmax out, duplicated pairs
#define SM_YP  21248     // 16384                 y partials (4x4096); g2p aliases [0,8192)
#define SM_T   37632     // 32*128 = 4096
#define SM_BLC 41728     // 64*36 = 2304          bl chunk [i][k] (also colsum scratch)
#define SM_SV  44032     // 1024
#define SM_SC  45056     // 32
#define SM_FLOATS 45088
#define SMEM_BYTES (SM_FLOATS * 4)

__global__ __launch_bounds__(NT, 1)
void caps_routing_kernel(const float* __restrict__ X,
                         const float* __restrict__ W,
                         float* __restrict__ out)
{
    extern __shared__ float sm[];
    float* xs  = sm + SM_XS;
    float* c2  = sm + SM_C2;
    float* yp  = sm + SM_YP;
    float* g2p = sm + SM_YP;      // alias: used only inside chunks, yp only after
    float* Tm  = sm + SM_T;
    float* blc = sm + SM_BLC;
    float* sv  = sm + SM_SV;
    float* scl = sm + SM_SC;

    const int b    = blockIdx.x;
    const int t    = threadIdx.x;
    const int lane = t & 31;
    const int w    = t >> 5;      // 16 warps

    const float* __restrict__ xg = X + (size_t)b * (II * JJ);
    float* __restrict__ blg = g_bl + (size_t)b * (KK * II);

    // GEMM1 warp mapping: kg1 in [0,4) -> 8 k ; is1 in [0,4) -> 16 i per chunk
    const int kg1 = w & 3, is1 = w >> 2;
    // GEMM2 warp mapping: kg2 in [0,2) -> 16 k ; ig2 in [0,2) -> 32 i ; js2 in [0,4) -> 32 j
    const int kg2 = w & 1, ig2 = (w >> 1) & 1, js2 = w >> 2;

    // ================= it0: y[k][j] = (1/32) sum_i x[i][j] =================
    {
        u64 s0 = 0, s1 = 0;
        const float* xp = xg + (size_t)(w * 72) * JJ + lane * 4;
        #pragma unroll 4
        for (int ii = 0; ii < 72; ++ii) {
            ulonglong2 v = *(const ulonglong2*)(xp + (size_t)ii * JJ);
            ADD2(s0, s0, v.x); ADD2(s1, s1, v.y);
        }
        ((ulonglong2*)yp)[w * 32 + lane] = make_ulonglong2(s0, s1);
        __syncthreads();
        if (t < 32) {
            u64 a0 = 0, a1 = 0;
            #pragma unroll
            for (int p = 0; p < 16; ++p) {
                ulonglong2 v = ((ulonglong2*)yp)[p * 32 + t];
                ADD2(a0, a0, v.x); ADD2(a1, a1, v.y);
            }
            const unsigned int ui = __float_as_uint(1.0f / 32.0f);
            const u64 sc2 = (u64)ui | ((u64)ui << 32);
            MUL2(a0, a0, sc2); MUL2(a1, a1, sc2);
            ((ulonglong2*)blc)[t] = make_ulonglong2(a0, a1);   // blc as scratch
        }
        __syncthreads();
        #pragma unroll
        for (int pp = 0; pp < 2; ++pp) {
            const int e4 = t + pp * NT;                        // e4 = k*32 + j4
            ((ulonglong2*)yp)[e4] = ((const ulonglong2*)blc)[e4 & 31];
        }
        __syncthreads();
    }

    for (int trans = 0; trans <= 1; ++trans) {
        // ===== s[k][d] = sum_j y[k][j] W[j,k,d] =====
        #pragma unroll
        for (int pp = 0; pp < 2; ++pp) {
            const int p = t + pp * NT;
            const int k = p >> 5, d = p & 31;
            const float* Wp = W + k * DD + d;
            const float* yk = yp + k * JJ;
            float acc = 0.f;
            #pragma unroll 8
            for (int j = 0; j < JJ; ++j)
                acc = fmaf(yk[j], Wp[(size_t)j * KD], acc);
            sv[p] = acc;
        }
        __syncthreads();
        // ===== squash =====
        if (t < KK) {
            float ss = 0.f;
            #pragma unroll
            for (int d = 0; d < DD; ++d) { const float q = sv[t * DD + d]; ss += q * q; }
            scl[t] = ss / (1.0f + ss) * rsqrtf(ss + 1e-7f);
        }
        __syncthreads();
        #pragma unroll
        for (int pp = 0; pp < 2; ++pp) {
            const int p = t + pp * NT;
            sv[p] *= scl[p >> 5];
        }
        __syncthreads();

        // ===== T[k][j] = sum_d v[k][d] W[j,k,d]  (smem-transposed W) =====
        {
            float* wt = xs + w * 1056;
            #pragma unroll
            for (int kk = 0; kk < 2; ++kk) {
                const int k = 2 * w + kk;
                #pragma unroll
                for (int jb = 0; jb < 4; ++jb) {
                    #pragma unroll 8
                    for (int j2 = 0; j2 < 32; ++j2)
                        wt[lane * 33 + j2] = W[(size_t)(jb * 32 + j2) * KD + k * DD + lane];
                    __syncwarp();
                    float acc = 0.f;
                    #pragma unroll
                    for (int d = 0; d < 32; ++d)
                        acc = fmaf(wt[d * 33 + lane], sv[k * DD + d], acc);
                    Tm[k * JJ + jb * 32 + lane] = acc;
                    __syncwarp();
                }
            }
        }
        __syncthreads();

        // ===== fused streaming pass: GEMM2 -> softmax -> GEMM1 per chunk =====
        u64 a1[8][2];
        #pragma unroll
        for (int q = 0; q < 8; ++q) { a1[q][0] = 0; a1[q][1] = 0; }

        // preload chunk 0
        {
            unsigned dbase = (unsigned)__cvta_generic_to_shared(xs);
            #pragma unroll
            for (int ee = 0; ee < 4; ++ee) {
                const int e4 = t + ee * NT;
                const int il = e4 >> 5, j4 = e4 & 31;
                unsigned d = dbase + (unsigned)(il * XPF + j4 * 4) * 4u;
                const float* s = xg + (size_t)il * JJ + j4 * 4;
                asm volatile("cp.async.cg.shared.global [%0], [%1], 16;\n" :: "r"(d), "l"(s));
            }
            CP_COMMIT();
        }

        for (int ch = 0; ch < NCHUNK; ++ch) {
            const int ibase = ch * CI;
            CP_WAIT0();
            __syncthreads();
            const float* xb = xs + (ch & 1) * XBUF;

            // prefetch next chunk (overlaps with compute below)
            if (ch + 1 < NCHUNK) {
                unsigned dbase = (unsigned)__cvta_generic_to_shared(xs + ((ch + 1) & 1) * XBUF);
                const float* src = xg + (size_t)(ibase + CI) * JJ;
                #pragma unroll
                for (int ee = 0; ee < 4; ++ee) {
                    const int e4 = t + ee * NT;
                    const int il = e4 >> 5, j4 = e4 & 31;
                    unsigned d = dbase + (unsigned)(il * XPF + j4 * 4) * 4u;
                    asm volatile("cp.async.cg.shared.global [%0], [%1], 16;\n"
                                 :: "r"(d), "l"(src + (size_t)il * JJ + j4 * 4));
                }
                CP_COMMIT();
            }

            // ---- GEMM2: 16 k x 32 i (lane) x 32 j per warp ----
            {
                u64 a2[16];
                #pragma unroll
                for (int kk = 0; kk < 16; ++kk) a2[kk] = 0;
                const float* xr = xb + (ig2 * 32 + lane) * XPF;
                #pragma unroll 2
                for (int st = 0; st < 8; ++st) {
                    const int jq = js2 * 8 + st;
                    ulonglong2 xv = *(const ulonglong2*)(xr + jq * 4);
                    #pragma unroll
                    for (int kk = 0; kk < 16; ++kk) {
                        const int k = kg2 * 16 + kk;
                        ulonglong2 tq = *(const ulonglong2*)(Tm + k * JJ + jq * 4); // bcast
                        FMA2(a2[kk], tq.x, xv.x, a2[kk]);
                        FMA2(a2[kk], tq.y, xv.y, a2[kk]);
                    }
                }
                #pragma unroll
                for (int kk = 0; kk < 16; ++kk) {
                    float2 f = *(float2*)&a2[kk];
                    g2p[js2 * 2048 + (kg2 * 16 + kk) * 64 + ig2 * 32 + lane] = f.x + f.y;
                }
            }
            __syncthreads();

            // ---- combine js partials, update blg, stash blc[i][k] ----
            #pragma unroll
            for (int ee = 0; ee < 4; ++ee) {
                const int e = t + ee * NT;
                const int k = e >> 6, iL = e & 63;
                float val = g2p[e] + g2p[2048 + e] + g2p[4096 + e] + g2p[6144 + e];
                const size_t gi = (size_t)k * II + ibase + iL;
                if (trans) val += blg[gi];
                blg[gi] = val;
                blc[iL * 36 + k] = val;
            }
            __syncthreads();

            // ---- softmax over k (8 threads per i, 4 k each) ----
            {
                const int i = t >> 3, kq = (t & 7) * 4;
                float4 v4 = *(const float4*)(blc + i * 36 + kq);
                float mx = fmaxf(fmaxf(v4.x, v4.y), fmaxf(v4.z, v4.w));
                #pragma unroll
                for (int off = 1; off < 8; off <<= 1)
                    mx = fmaxf(mx, __shfl_xor_sync(0xffffffffu, mx, off));
                const float e0 = __expf(v4.x - mx), e1 = __expf(v4.y - mx);
                const float e2 = __expf(v4.z - mx), e3 = __expf(v4.w - mx);
                float ssum = e0 + e1 + e2 + e3;
                #pragma unroll
                for (int off = 1; off < 8; off <<= 1)
                    ssum += __shfl_xor_sync(0xffffffffu, ssum, off);
                const float inv = 1.0f / ssum;
                float* cr = c2 + i * C2P + kq * 2;
                *(float4*)(cr)     = make_float4(e0 * inv, e0 * inv, e1 * inv, e1 * inv);
                *(float4*)(cr + 4) = make_float4(e2 * inv, e2 * inv, e3 * inv, e3 * inv);
            }
            __syncthreads();

            // ---- GEMM1 accumulate: 8 k x 16 i x 128 j (float4/lane) per warp ----
            #pragma unroll 2
            for (int ii = 0; ii < 16; ++ii) {
                const int i = is1 * 16 + ii;
                ulonglong2 xv = *(const ulonglong2*)(xb + i * XPF + lane * 4);
                const ulonglong2* cr = (const ulonglong2*)(c2 + i * C2P + kg1 * 16);
                #pragma unroll
                for (int q = 0; q < 4; ++q) {
                    ulonglong2 cq = cr[q];
                    FMA2(a1[2*q  ][0], cq.x, xv.x, a1[2*q  ][0]);
                    FMA2(a1[2*q  ][1], cq.x, xv.y, a1[2*q  ][1]);
                    FMA2(a1[2*q+1][0], cq.y, xv.x, a1[2*q+1][0]);
                    FMA2(a1[2*q+1][1], cq.y, xv.y, a1[2*q+1][1]);
                }
            }
            // next chunk's post-wait barrier orders these reads vs. buffer reuse
        }
        __syncthreads();
        // write GEMM1 partials and reduce 4 i-splits
        #pragma unroll
        for (int q = 0; q < 8; ++q) {
            const int k = kg1 * 8 + q;
            *(ulonglong2*)(yp + is1 * 4096 + k * JJ + lane * 4) =
                make_ulonglong2(a1[q][0], a1[q][1]);
        }
        __syncthreads();
        #pragma unroll
        for (int pp = 0; pp < 2; ++pp) {
            const int e4 = t + pp * NT;
            ulonglong2 a = ((ulonglong2*)yp)[e4];
            #pragma unroll
            for (int p = 1; p < 4; ++p) {
                ulonglong2 v = ((ulonglong2*)yp)[p * 1024 + e4];
                ADD2(a.x, a.x, v.x); ADD2(a.y, a.y, v.y);
            }
            ((ulonglong2*)yp)[e4] = a;
        }
        __syncthreads();
    }

    // ===== final: s = y*W, v = squash(s), write out =====
    #pragma unroll
    for (int pp = 0; pp < 2; ++pp) {
        const int p = t + pp * NT;
        const int k = p >> 5, d = p & 31;
        const float* Wp = W + k * DD + d;
        const float* yk = yp + k * JJ;
        float acc = 0.f;
        #pragma unroll 8
        for (int j = 0; j < JJ; ++j)
            acc = fmaf(yk[j], Wp[(size_t)j * KD], acc);
        sv[p] = acc;
    }
    __syncthreads();
    if (t < KK) {
        float ss = 0.f;
        #pragma unroll
        for (int d = 0; d < DD; ++d) { const float q = sv[t * DD + d]; ss += q * q; }
        scl[t] = ss / (1.0f + ss) * rsqrtf(ss + 1e-7f);
    }
    __syncthreads();
    #pragma unroll
    for (int pp = 0; pp < 2; ++pp) {
        const int p = t + pp * NT;
        out[(size_t)b * KD + p] = sv[p] * scl[p >> 5];
    }
}

extern "C" void kernel_launch(void* const* d_in, const int* in_sizes, int n_in,
                              void* d_out, int out_size)
{
    (void)in_sizes; (void)n_in; (void)out_size;
    const float* X = (const float*)d_in[0];   // [128, 1152, 128] f32
    const float* W = (const float*)d_in[1];   // [128, 32, 32] f32
    float* out = (float*)d_out;               // [128, 32, 32] f32

    cudaFuncSetAttribute(caps_routing_kernel,
                         cudaFuncAttributeMaxDynamicSharedMemorySize, SMEM_BYTES);
    caps_routing_kernel<<<BB, NT, SMEM_BYTES>>>(X, W, out);
}